// round 13
// baseline (speedup 1.0000x reference)
#include <cuda_runtime.h>
#include <cuda_bf16.h>

typedef unsigned int u32;

#define NPTS 3600
#define DD   128
#define HH   512
#define WW   512
#define NPB  900
#define WC   30
#define SCOLS 3601   // 1 + NPTS
#define SPITCH 40    // bf16 elements per smem row (conflict-free)
#define GEMM_BLOCKS (29 * 29)   // 841 tiles of 128x128
#define MATCH_BLOCKS (NPTS / 2) // 1800 blocks, 2 points per block

// ---------------- scratch (static device globals) ---------------------------
__device__ int   g_y1[NPTS], g_x1[NPTS];
__device__ int   g_yd[NPTS], g_xd[NPTS];
__device__ int   g_xy2x[NPTS], g_xy2y[NPTS];
__device__ float g_A[NPTS * DD];
__device__ uint4 g_Ahi[NPTS * DD / 8];
__device__ uint4 g_Alo[NPTS * DD / 8];
__device__ uint4 g_Bhi[NPTS * DD / 8];
__device__ uint4 g_Blo[NPTS * DD / 8];

__constant__ int c_OI[13] = {-2,-1,-1,-1, 0, 0, 0, 0, 0, 1, 1, 1, 2};
__constant__ int c_OJ[13] = { 0,-1, 0, 1,-2,-1, 0, 1, 2,-1, 0, 1, 0};

// ---------------- kernel 1: per-cell argmax sample + descriptor gather ------
// which==0 blocks additionally compute xy2 (warped coords) from aflow, so the
// fused kernel has NO intra-launch dependencies.
__global__ void k_sample(const float* __restrict__ det1, const float* __restrict__ des1,
                         const float* __restrict__ det2, const float* __restrict__ des2,
                         const float* __restrict__ aflow)
{
    const int c = blockIdx.x;
    const int which = blockIdx.y;
    const float* det = which ? det2 : det1;
    const float* des = which ? des2 : des1;

    const int b = c / NPB;
    const int cell = c % NPB;
    const int hc = cell / WC;
    const int wc = cell % WC;
    const int t = threadIdx.x;
    const int row = 16 + hc * 16 + (t >> 4);
    const int col = 16 + wc * 16 + (t & 15);

    float v = det[((size_t)b * HH + row) * WW + col];

    __shared__ float sv[256];
    __shared__ int   si[256];
    sv[t] = v;
    si[t] = t;
    __syncthreads();
    for (int s = 128; s > 0; s >>= 1) {
        if (t < s) {
            float v2 = sv[t + s];
            int i2 = si[t + s];
            if (v2 > sv[t] || (v2 == sv[t] && i2 < si[t])) { sv[t] = v2; si[t] = i2; }
        }
        __syncthreads();
    }
    const int best = si[0];
    const int brow = 16 + hc * 16 + (best >> 4);  // axis3 index (x1 / xd)
    const int bcol = 16 + wc * 16 + (best & 15);  // axis2 index (y1 / yd)

    if (t == 0) {
        if (which == 0) {
            g_y1[c] = bcol;
            g_x1[c] = brow;
            // warped coordinates (consumed by both fused paths)
            const float ax = aflow[(((size_t)b * 2 + 0) * HH + bcol) * WW + brow];
            const float ay = aflow[(((size_t)b * 2 + 1) * HH + bcol) * WW + brow];
            g_xy2x[c] = (int)(ax + 0.5f);
            g_xy2y[c] = (int)(ay + 0.5f);
        } else {
            g_yd[c] = bcol;
            g_xd[c] = brow;
        }
    }
    if (t < DD) {
        float d = des[(((size_t)b * DD + t) * HH + bcol) * WW + brow];
        __nv_bfloat16 hi = __float2bfloat16(d);
        __nv_bfloat16 lo = __float2bfloat16(d - __bfloat162float(hi));
        const size_t idx = (size_t)c * DD + t;
        if (which == 0) {
            g_A[idx] = d;
            ((__nv_bfloat16*)g_Ahi)[idx] = hi;
            ((__nv_bfloat16*)g_Alo)[idx] = lo;
        } else {
            ((__nv_bfloat16*)g_Bhi)[idx] = hi;
            ((__nv_bfloat16*)g_Blo)[idx] = lo;
        }
    }
}

// ---------------- fused kernel 2: gemm blocks + match blocks ----------------
__device__ __forceinline__ void mma_bf16(float* c, const u32* a, const u32* b)
{
    asm volatile("mma.sync.aligned.m16n8k16.row.col.f32.bf16.bf16.f32 "
                 "{%0,%1,%2,%3}, {%4,%5,%6,%7}, {%8,%9}, {%0,%1,%2,%3};"
                 : "+f"(c[0]), "+f"(c[1]), "+f"(c[2]), "+f"(c[3])
                 : "r"(a[0]), "r"(a[1]), "r"(a[2]), "r"(a[3]), "r"(b[0]), "r"(b[1]));
}

__global__ void __launch_bounds__(256)
k_fused(const float* __restrict__ des2,
        const float* __restrict__ qlt1, const float* __restrict__ qlt2,
        float* __restrict__ out_scores, float* __restrict__ out_lab,
        float* __restrict__ out_mask, float* __restrict__ out_qlt)
{
    __shared__ __align__(16) __nv_bfloat16 sAhi[128 * SPITCH];
    __shared__ __align__(16) __nv_bfloat16 sAlo[128 * SPITCH];
    __shared__ __align__(16) __nv_bfloat16 sBhi[128 * SPITCH];
    __shared__ __align__(16) __nv_bfloat16 sBlo[128 * SPITCH];
    __shared__ float sred[8][13];

    const int tid = threadIdx.x;

    if (blockIdx.x >= GEMM_BLOCKS) {
        // ==================== MATCH PATH: 2 keypoints per block =============
        const int grp  = tid >> 7;            // 0/1: which keypoint
        const int tl   = tid & 127;           // d channel 0..127
        const int lane = tl & 31;
        const int warp = tl >> 5;
        const int n = (blockIdx.x - GEMM_BLOCKS) * 2 + grp;

        const int b  = n / NPB;
        const int xx = g_xy2x[n];
        const int yy = g_xy2y[n];

        const float s = g_A[(size_t)n * DD + tl];

        const float* base = des2 + (size_t)b * DD * HH * WW + (size_t)tl * HH * WW;

        float val[13];
        #pragma unroll
        for (int k = 0; k < 13; k++) {
            int px = xx + c_OI[k]; px = px < 0 ? 0 : (px > WW - 1 ? WW - 1 : px);
            int py = yy + c_OJ[k]; py = py < 0 ? 0 : (py > HH - 1 ? HH - 1 : py);
            val[k] = s * __ldg(&base[(size_t)py * WW + px]);
        }

        #pragma unroll
        for (int k = 0; k < 13; k++) {
            #pragma unroll
            for (int off = 16; off > 0; off >>= 1)
                val[k] += __shfl_xor_sync(0xffffffffu, val[k], off);
        }

        if (lane == 0) {
            #pragma unroll
            for (int k = 0; k < 13; k++) sred[grp * 4 + warp][k] = val[k];
        }
        __syncthreads();

        if (tl == 0) {
            float dots[13];
            #pragma unroll
            for (int k = 0; k < 13; k++)
                dots[k] = sred[grp * 4 + 0][k] + sred[grp * 4 + 1][k]
                        + sred[grp * 4 + 2][k] + sred[grp * 4 + 3][k];

            float best = dots[0];
            int pos = 0;
            #pragma unroll
            for (int k = 1; k < 13; k++)
                if (dots[k] > best) { best = dots[k]; pos = k; }

            const int y1 = g_y1[n];
            const int x1 = g_x1[n];
            const bool msk = (xx >= 0) && (yy >= 0) && (xx < WW) && (yy < HH);
            int sx = xx + c_OI[pos]; sx = sx < 0 ? 0 : (sx > WW - 1 ? WW - 1 : sx);
            int sy = yy + c_OJ[pos]; sy = sy < 0 ? 0 : (sy > HH - 1 ? HH - 1 : sy);
            float q = 0.5f * (qlt1[((size_t)b * HH + y1) * WW + x1] +
                              qlt2[((size_t)b * HH + sy) * WW + sx]);
            out_scores[(size_t)n * SCOLS] = best;
            out_lab[(size_t)n * SCOLS]    = 1.0f;
            out_qlt[n]  = q;
            out_mask[n] = msk ? 1.0f : 0.0f;
        }
        return;
    }

    // ==================== GEMM PATH (identical to passing R8 body) ==========
    const int warp   = tid >> 5;
    const int lane   = tid & 31;
    const int warp_m = warp >> 2;      // 0..1
    const int warp_n = warp & 3;       // 0..3
    const int m0 = (blockIdx.x / 29) * 128;
    const int n0 = (blockIdx.x % 29) * 128;

    const int g  = lane >> 2;          // fragment group row 0..7
    const int cp = (lane & 3) * 2;     // fragment col pair 0,2,4,6

    float acc[4][4][4];
    #pragma unroll
    for (int mt = 0; mt < 4; mt++) {
        #pragma unroll
        for (int nt = 0; nt < 4; nt++) {
            acc[mt][nt][0] = 0.f; acc[mt][nt][1] = 0.f;
            acc[mt][nt][2] = 0.f; acc[mt][nt][3] = 0.f;
        }
    }

    const int lr = tid >> 1;            // 0..127: tile row to load
    const int kh = (tid & 1) * 16;      // 16-elem half of the 32-k chunk

    for (int kc = 0; kc < DD; kc += 32) {
        __syncthreads();
        uint4 z = make_uint4(0u, 0u, 0u, 0u);
        uint4 vah0 = z, vah1 = z, vlo0 = z, vlo1 = z;
        uint4 vbh0 = z, vbh1 = z, vbl0 = z, vbl1 = z;
        const int ar = m0 + lr;
        const int br = n0 + lr;
        const int gi = (kc + kh) >> 3;              // uint4 index within row
        if (ar < NPTS) {
            vah0 = g_Ahi[(size_t)ar * (DD / 8) + gi];
            vah1 = g_Ahi[(size_t)ar * (DD / 8) + gi + 1];
            vlo0 = g_Alo[(size_t)ar * (DD / 8) + gi];
            vlo1 = g_Alo[(size_t)ar * (DD / 8) + gi + 1];
        }
        if (br < NPTS) {
            vbh0 = g_Bhi[(size_t)br * (DD / 8) + gi];
            vbh1 = g_Bhi[(size_t)br * (DD / 8) + gi + 1];
            vbl0 = g_Blo[(size_t)br * (DD / 8) + gi];
            vbl1 = g_Blo[(size_t)br * (DD / 8) + gi + 1];
        }
        *(uint4*)&sAhi[lr * SPITCH + kh]     = vah0;
        *(uint4*)&sAhi[lr * SPITCH + kh + 8] = vah1;
        *(uint4*)&sAlo[lr * SPITCH + kh]     = vlo0;
        *(uint4*)&sAlo[lr * SPITCH + kh + 8] = vlo1;
        *(uint4*)&sBhi[lr * SPITCH + kh]     = vbh0;
        *(uint4*)&sBhi[lr * SPITCH + kh + 8] = vbh1;
        *(uint4*)&sBlo[lr * SPITCH + kh]     = vbl0;
        *(uint4*)&sBlo[lr * SPITCH + kh + 8] = vbl1;
        __syncthreads();

        #pragma unroll
        for (int ks = 0; ks < 32; ks += 16) {
            u32 Ahf[4][4];
            u32 Alf[4][4];
            u32 Bhf[4][2];
            u32 Blf[4][2];

            #pragma unroll
            for (int mt = 0; mt < 4; mt++) {
                const int r0 = warp_m * 64 + mt * 16 + g;
                const int r8 = r0 + 8;
                const int c0 = ks + cp;
                Ahf[mt][0] = *(const u32*)&sAhi[r0 * SPITCH + c0];
                Ahf[mt][1] = *(const u32*)&sAhi[r8 * SPITCH + c0];
                Ahf[mt][2] = *(const u32*)&sAhi[r0 * SPITCH + c0 + 8];
                Ahf[mt][3] = *(const u32*)&sAhi[r8 * SPITCH + c0 + 8];
                Alf[mt][0] = *(const u32*)&sAlo[r0 * SPITCH + c0];
                Alf[mt][1] = *(const u32*)&sAlo[r8 * SPITCH + c0];
                Alf[mt][2] = *(const u32*)&sAlo[r0 * SPITCH + c0 + 8];
                Alf[mt][3] = *(const u32*)&sAlo[r8 * SPITCH + c0 + 8];
            }
            #pragma unroll
            for (int nt = 0; nt < 4; nt++) {
                const int rn = warp_n * 32 + nt * 8 + g;
                const int c0 = ks + cp;
                Bhf[nt][0] = *(const u32*)&sBhi[rn * SPITCH + c0];
                Bhf[nt][1] = *(const u32*)&sBhi[rn * SPITCH + c0 + 8];
                Blf[nt][0] = *(const u32*)&sBlo[rn * SPITCH + c0];
                Blf[nt][1] = *(const u32*)&sBlo[rn * SPITCH + c0 + 8];
            }
            #pragma unroll
            for (int mt = 0; mt < 4; mt++) {
                #pragma unroll
                for (int nt = 0; nt < 4; nt++) {
                    mma_bf16(acc[mt][nt], Ahf[mt], Bhf[nt]);
                    mma_bf16(acc[mt][nt], Ahf[mt], Blf[nt]);
                    mma_bf16(acc[mt][nt], Alf[mt], Bhf[nt]);
                }
            }
        }
    }

    // ---- epilogue: distance mask, write scores[:,1:] and labels[:,1:]=0 ----
    int rX[8], rY[8], rB[8], rI[8];
    #pragma unroll
    for (int idx = 0; idx < 8; idx++) {
        int mt = idx >> 1;
        int h  = idx & 1;
        int i  = m0 + warp_m * 64 + mt * 16 + g + h * 8;
        rI[idx] = (i < NPTS) ? i : -1;
        int iw = (i < NPTS) ? i : 0;
        rX[idx] = g_xy2x[iw];
        rY[idx] = g_xy2y[iw];
        rB[idx] = iw / NPB;
    }
    int cX[8], cY[8], cB[8], cJ[8];
    #pragma unroll
    for (int idx = 0; idx < 8; idx++) {
        int nt = idx >> 1;
        int e  = idx & 1;
        int j  = n0 + warp_n * 32 + nt * 8 + cp + e;
        cJ[idx] = (j < NPTS) ? j : -1;
        int jw = (j < NPTS) ? j : 0;
        cX[idx] = g_xd[jw];
        cY[idx] = g_yd[jw];
        cB[idx] = jw / NPB;
    }

    #pragma unroll
    for (int mt = 0; mt < 4; mt++) {
        #pragma unroll
        for (int nt = 0; nt < 4; nt++) {
            #pragma unroll
            for (int r = 0; r < 4; r++) {
                int ridx = mt * 2 + (r >> 1);
                int cidx = nt * 2 + (r & 1);
                int i = rI[ridx];
                int j = cJ[cidx];
                if (i < 0 || j < 0) continue;
                int dx = cX[cidx] - rX[ridx];
                int dy = cY[cidx] - rY[ridx];
                int dis2 = dx * dx + dy * dy + ((cB[cidx] != rB[ridx]) ? 4 : 0);
                float vout = (dis2 < 4) ? 0.f : acc[mt][nt][r];
                size_t o = (size_t)i * SCOLS + 1 + j;
                out_scores[o] = vout;
                out_lab[o] = 0.0f;
            }
        }
    }
}

// ---------------- launch ----------------------------------------------------
extern "C" void kernel_launch(void* const* d_in, const int* in_sizes, int n_in,
                              void* d_out, int out_size)
{
    const float* des1  = (const float*)d_in[0];
    const float* det1  = (const float*)d_in[1];
    const float* qlt1  = (const float*)d_in[2];
    const float* des2  = (const float*)d_in[3];
    const float* det2  = (const float*)d_in[4];
    const float* qlt2  = (const float*)d_in[5];
    const float* aflow = (const float*)d_in[6];

    float* out        = (float*)d_out;
    float* out_scores = out;                                     // (3600, 3601)
    float* out_lab    = out + (size_t)NPTS * SCOLS;              // (3600, 3601)
    float* out_mask   = out_lab + (size_t)NPTS * SCOLS;          // (4, 900)
    float* out_qlt    = out_mask + NPTS;                         // (3600, 1)

    dim3 gs(NPTS, 2);
    k_sample<<<gs, 256>>>(det1, des1, det2, des2, aflow);

    k_fused<<<GEMM_BLOCKS + MATCH_BLOCKS, 256>>>(des2, qlt1, qlt2,
                                                 out_scores, out_lab, out_mask, out_qlt);
}

// round 14
// speedup vs baseline: 1.0570x; 1.0570x over previous
#include <cuda_runtime.h>
#include <cuda_bf16.h>

typedef unsigned int u32;

#define NPTS 3600
#define DD   128
#define HH   512
#define WW   512
#define NPB  900
#define WC   30
#define SCOLS 3601   // 1 + NPTS
#define SPITCH 40    // bf16 elements per smem row (conflict-free)

// ---------------- scratch (static device globals) ---------------------------
__device__ int   g_y1[NPTS], g_x1[NPTS];
__device__ int   g_yd[NPTS], g_xd[NPTS];
__device__ int   g_xy2x[NPTS], g_xy2y[NPTS];
__device__ float g_A[NPTS * DD];
__device__ uint4 g_Ahi[NPTS * DD / 8];
__device__ uint4 g_Alo[NPTS * DD / 8];
__device__ uint4 g_Bhi[NPTS * DD / 8];
__device__ uint4 g_Blo[NPTS * DD / 8];

__constant__ int c_OI[13] = {-2,-1,-1,-1, 0, 0, 0, 0, 0, 1, 1, 1, 2};
__constant__ int c_OJ[13] = { 0,-1, 0, 1,-2,-1, 0, 1, 2,-1, 0, 1, 0};

// ---------------- kernel 1: per-cell argmax sample + descriptor gather ------
__global__ void k_sample(const float* __restrict__ det1, const float* __restrict__ des1,
                         const float* __restrict__ det2, const float* __restrict__ des2,
                         const float* __restrict__ aflow)
{
    const int c = blockIdx.x;
    const int which = blockIdx.y;
    const float* det = which ? det2 : det1;
    const float* des = which ? des2 : des1;

    const int b = c / NPB;
    const int cell = c % NPB;
    const int hc = cell / WC;
    const int wc = cell % WC;
    const int t = threadIdx.x;
    const int row = 16 + hc * 16 + (t >> 4);
    const int col = 16 + wc * 16 + (t & 15);

    float v = det[((size_t)b * HH + row) * WW + col];

    __shared__ float sv[256];
    __shared__ int   si[256];
    sv[t] = v;
    si[t] = t;
    __syncthreads();
    for (int s = 128; s > 0; s >>= 1) {
        if (t < s) {
            float v2 = sv[t + s];
            int i2 = si[t + s];
            if (v2 > sv[t] || (v2 == sv[t] && i2 < si[t])) { sv[t] = v2; si[t] = i2; }
        }
        __syncthreads();
    }
    const int best = si[0];
    const int brow = 16 + hc * 16 + (best >> 4);  // axis3 index (x1 / xd)
    const int bcol = 16 + wc * 16 + (best & 15);  // axis2 index (y1 / yd)

    if (t == 0) {
        if (which == 0) {
            g_y1[c] = bcol;
            g_x1[c] = brow;
            const float ax = aflow[(((size_t)b * 2 + 0) * HH + bcol) * WW + brow];
            const float ay = aflow[(((size_t)b * 2 + 1) * HH + bcol) * WW + brow];
            g_xy2x[c] = (int)(ax + 0.5f);
            g_xy2y[c] = (int)(ay + 0.5f);
        } else {
            g_yd[c] = bcol;
            g_xd[c] = brow;
        }
    }
    if (t < DD) {
        float d = des[(((size_t)b * DD + t) * HH + bcol) * WW + brow];
        __nv_bfloat16 hi = __float2bfloat16(d);
        __nv_bfloat16 lo = __float2bfloat16(d - __bfloat162float(hi));
        const size_t idx = (size_t)c * DD + t;
        if (which == 0) {
            g_A[idx] = d;
            ((__nv_bfloat16*)g_Ahi)[idx] = hi;
            ((__nv_bfloat16*)g_Alo)[idx] = lo;
        } else {
            ((__nv_bfloat16*)g_Bhi)[idx] = hi;
            ((__nv_bfloat16*)g_Blo)[idx] = lo;
        }
    }
}

// ---------------- kernel 2: neighbor matching (one BLOCK per keypoint) ------
__global__ void __launch_bounds__(128)
k_match(const float* __restrict__ des2,
        const float* __restrict__ qlt1, const float* __restrict__ qlt2,
        float* __restrict__ out_scores, float* __restrict__ out_lab,
        float* __restrict__ out_mask, float* __restrict__ out_qlt)
{
    const int n = blockIdx.x;
    const int t = threadIdx.x;        // d channel 0..127
    const int lane = t & 31;
    const int warp = t >> 5;

    const int b  = n / NPB;
    const int xx = g_xy2x[n];
    const int yy = g_xy2y[n];

    const float s = g_A[(size_t)n * DD + t];

    const float* base = des2 + (size_t)b * DD * HH * WW + (size_t)t * HH * WW;

    float val[13];
    #pragma unroll
    for (int k = 0; k < 13; k++) {
        int px = xx + c_OI[k]; px = px < 0 ? 0 : (px > WW - 1 ? WW - 1 : px);
        int py = yy + c_OJ[k]; py = py < 0 ? 0 : (py > HH - 1 ? HH - 1 : py);
        val[k] = s * __ldg(&base[(size_t)py * WW + px]);
    }

    #pragma unroll
    for (int k = 0; k < 13; k++) {
        #pragma unroll
        for (int off = 16; off > 0; off >>= 1)
            val[k] += __shfl_xor_sync(0xffffffffu, val[k], off);
    }

    __shared__ float sred[4][13];
    if (lane == 0) {
        #pragma unroll
        for (int k = 0; k < 13; k++) sred[warp][k] = val[k];
    }
    __syncthreads();

    if (t == 0) {
        float dots[13];
        #pragma unroll
        for (int k = 0; k < 13; k++)
            dots[k] = sred[0][k] + sred[1][k] + sred[2][k] + sred[3][k];

        float best = dots[0];
        int pos = 0;
        #pragma unroll
        for (int k = 1; k < 13; k++)
            if (dots[k] > best) { best = dots[k]; pos = k; }

        const int y1 = g_y1[n];
        const int x1 = g_x1[n];
        const bool msk = (xx >= 0) && (yy >= 0) && (xx < WW) && (yy < HH);
        int sx = xx + c_OI[pos]; sx = sx < 0 ? 0 : (sx > WW - 1 ? WW - 1 : sx);
        int sy = yy + c_OJ[pos]; sy = sy < 0 ? 0 : (sy > HH - 1 ? HH - 1 : sy);
        float q = 0.5f * (qlt1[((size_t)b * HH + y1) * WW + x1] +
                          qlt2[((size_t)b * HH + sy) * WW + sx]);
        out_scores[(size_t)n * SCOLS] = best;
        out_lab[(size_t)n * SCOLS]    = 1.0f;
        out_qlt[n]  = q;
        out_mask[n] = msk ? 1.0f : 0.0f;
    }
}

// ---------------- kernel 3: bf16x3 tensor-core GEMM + mask + labels --------
__device__ __forceinline__ void mma_bf16(float* c, const u32* a, const u32* b)
{
    asm volatile("mma.sync.aligned.m16n8k16.row.col.f32.bf16.bf16.f32 "
                 "{%0,%1,%2,%3}, {%4,%5,%6,%7}, {%8,%9}, {%0,%1,%2,%3};"
                 : "+f"(c[0]), "+f"(c[1]), "+f"(c[2]), "+f"(c[3])
                 : "r"(a[0]), "r"(a[1]), "r"(a[2]), "r"(a[3]), "r"(b[0]), "r"(b[1]));
}

__global__ void __launch_bounds__(256, 1)
k_gemm(float* __restrict__ out_scores, float* __restrict__ out_lab)
{
    __shared__ __align__(16) __nv_bfloat16 sAhi[128 * SPITCH];
    __shared__ __align__(16) __nv_bfloat16 sAlo[128 * SPITCH];
    __shared__ __align__(16) __nv_bfloat16 sBhi[128 * SPITCH];
    __shared__ __align__(16) __nv_bfloat16 sBlo[128 * SPITCH];

    const int tid    = threadIdx.x;
    const int warp   = tid >> 5;
    const int lane   = tid & 31;
    const int warp_m = warp >> 2;      // 0..1
    const int warp_n = warp & 3;       // 0..3
    const int m0 = blockIdx.y * 128;
    const int n0 = blockIdx.x * 128;

    const int g  = lane >> 2;          // fragment group row 0..7
    const int cp = (lane & 3) * 2;     // fragment col pair 0,2,4,6

    float acc[4][4][4];
    #pragma unroll
    for (int mt = 0; mt < 4; mt++) {
        #pragma unroll
        for (int nt = 0; nt < 4; nt++) {
            acc[mt][nt][0] = 0.f; acc[mt][nt][1] = 0.f;
            acc[mt][nt][2] = 0.f; acc[mt][nt][3] = 0.f;
        }
    }

    const int lr = tid >> 1;            // 0..127: tile row to load
    const int kh = (tid & 1) * 16;      // 16-elem half of the 32-k chunk

    for (int kc = 0; kc < DD; kc += 32) {
        __syncthreads();
        uint4 z = make_uint4(0u, 0u, 0u, 0u);
        uint4 vah0 = z, vah1 = z, vlo0 = z, vlo1 = z;
        uint4 vbh0 = z, vbh1 = z, vbl0 = z, vbl1 = z;
        const int ar = m0 + lr;
        const int br = n0 + lr;
        const int gi = (kc + kh) >> 3;              // uint4 index within row
        if (ar < NPTS) {
            vah0 = g_Ahi[(size_t)ar * (DD / 8) + gi];
            vah1 = g_Ahi[(size_t)ar * (DD / 8) + gi + 1];
            vlo0 = g_Alo[(size_t)ar * (DD / 8) + gi];
            vlo1 = g_Alo[(size_t)ar * (DD / 8) + gi + 1];
        }
        if (br < NPTS) {
            vbh0 = g_Bhi[(size_t)br * (DD / 8) + gi];
            vbh1 = g_Bhi[(size_t)br * (DD / 8) + gi + 1];
            vbl0 = g_Blo[(size_t)br * (DD / 8) + gi];
            vbl1 = g_Blo[(size_t)br * (DD / 8) + gi + 1];
        }
        *(uint4*)&sAhi[lr * SPITCH + kh]     = vah0;
        *(uint4*)&sAhi[lr * SPITCH + kh + 8] = vah1;
        *(uint4*)&sAlo[lr * SPITCH + kh]     = vlo0;
        *(uint4*)&sAlo[lr * SPITCH + kh + 8] = vlo1;
        *(uint4*)&sBhi[lr * SPITCH + kh]     = vbh0;
        *(uint4*)&sBhi[lr * SPITCH + kh + 8] = vbh1;
        *(uint4*)&sBlo[lr * SPITCH + kh]     = vbl0;
        *(uint4*)&sBlo[lr * SPITCH + kh + 8] = vbl1;
        __syncthreads();

        #pragma unroll
        for (int ks = 0; ks < 32; ks += 16) {
            u32 Ahf[4][4];
            u32 Alf[4][4];
            u32 Bhf[4][2];
            u32 Blf[4][2];

            #pragma unroll
            for (int mt = 0; mt < 4; mt++) {
                const int r0 = warp_m * 64 + mt * 16 + g;
                const int r8 = r0 + 8;
                const int c0 = ks + cp;
                Ahf[mt][0] = *(const u32*)&sAhi[r0 * SPITCH + c0];
                Ahf[mt][1] = *(const u32*)&sAhi[r8 * SPITCH + c0];
                Ahf[mt][2] = *(const u32*)&sAhi[r0 * SPITCH + c0 + 8];
                Ahf[mt][3] = *(const u32*)&sAhi[r8 * SPITCH + c0 + 8];
                Alf[mt][0] = *(const u32*)&sAlo[r0 * SPITCH + c0];
                Alf[mt][1] = *(const u32*)&sAlo[r8 * SPITCH + c0];
                Alf[mt][2] = *(const u32*)&sAlo[r0 * SPITCH + c0 + 8];
                Alf[mt][3] = *(const u32*)&sAlo[r8 * SPITCH + c0 + 8];
            }
            #pragma unroll
            for (int nt = 0; nt < 4; nt++) {
                const int rn = warp_n * 32 + nt * 8 + g;
                const int c0 = ks + cp;
                Bhf[nt][0] = *(const u32*)&sBhi[rn * SPITCH + c0];
                Bhf[nt][1] = *(const u32*)&sBhi[rn * SPITCH + c0 + 8];
                Blf[nt][0] = *(const u32*)&sBlo[rn * SPITCH + c0];
                Blf[nt][1] = *(const u32*)&sBlo[rn * SPITCH + c0 + 8];
            }
            #pragma unroll
            for (int mt = 0; mt < 4; mt++) {
                #pragma unroll
                for (int nt = 0; nt < 4; nt++) {
                    mma_bf16(acc[mt][nt], Ahf[mt], Bhf[nt]);
                    mma_bf16(acc[mt][nt], Ahf[mt], Blf[nt]);
                    mma_bf16(acc[mt][nt], Alf[mt], Bhf[nt]);
                }
            }
        }
    }

    // ---- epilogue: distance mask, write scores[:,1:] and labels[:,1:]=0 ----
    int rX[8], rY[8], rB[8], rI[8];
    #pragma unroll
    for (int idx = 0; idx < 8; idx++) {
        int mt = idx >> 1;
        int h  = idx & 1;
        int i  = m0 + warp_m * 64 + mt * 16 + g + h * 8;
        rI[idx] = (i < NPTS) ? i : -1;
        int iw = (i < NPTS) ? i : 0;
        rX[idx] = g_xy2x[iw];
        rY[idx] = g_xy2y[iw];
        rB[idx] = iw / NPB;
    }
    int cX[8], cY[8], cB[8], cJ[8];
    #pragma unroll
    for (int idx = 0; idx < 8; idx++) {
        int nt = idx >> 1;
        int e  = idx & 1;
        int j  = n0 + warp_n * 32 + nt * 8 + cp + e;
        cJ[idx] = (j < NPTS) ? j : -1;
        int jw = (j < NPTS) ? j : 0;
        cX[idx] = g_xd[jw];
        cY[idx] = g_yd[jw];
        cB[idx] = jw / NPB;
    }

    #pragma unroll
    for (int mt = 0; mt < 4; mt++) {
        #pragma unroll
        for (int nt = 0; nt < 4; nt++) {
            #pragma unroll
            for (int r = 0; r < 4; r++) {
                int ridx = mt * 2 + (r >> 1);
                int cidx = nt * 2 + (r & 1);
                int i = rI[ridx];
                int j = cJ[cidx];
                if (i < 0 || j < 0) continue;
                int dx = cX[cidx] - rX[ridx];
                int dy = cY[cidx] - rY[ridx];
                int dis2 = dx * dx + dy * dy + ((cB[cidx] != rB[ridx]) ? 4 : 0);
                float vout = (dis2 < 4) ? 0.f : acc[mt][nt][r];
                size_t o = (size_t)i * SCOLS + 1 + j;
                out_scores[o] = vout;
                out_lab[o] = 0.0f;
            }
        }
    }
}

// ---------------- launch: fork/join so match and gemm overlap ---------------
extern "C" void kernel_launch(void* const* d_in, const int* in_sizes, int n_in,
                              void* d_out, int out_size)
{
    static cudaStream_t s2 = 0;
    static cudaEvent_t ev_fork = 0, ev_join = 0;
    if (s2 == 0) {
        cudaStreamCreateWithFlags(&s2, cudaStreamNonBlocking);
        cudaEventCreateWithFlags(&ev_fork, cudaEventDisableTiming);
        cudaEventCreateWithFlags(&ev_join, cudaEventDisableTiming);
    }

    const float* des1  = (const float*)d_in[0];
    const float* det1  = (const float*)d_in[1];
    const float* qlt1  = (const float*)d_in[2];
    const float* des2  = (const float*)d_in[3];
    const float* det2  = (const float*)d_in[4];
    const float* qlt2  = (const float*)d_in[5];
    const float* aflow = (const float*)d_in[6];

    float* out        = (float*)d_out;
    float* out_scores = out;                                     // (3600, 3601)
    float* out_lab    = out + (size_t)NPTS * SCOLS;              // (3600, 3601)
    float* out_mask   = out_lab + (size_t)NPTS * SCOLS;          // (4, 900)
    float* out_qlt    = out_mask + NPTS;                         // (3600, 1)

    dim3 gs(NPTS, 2);
    k_sample<<<gs, 256>>>(det1, des1, det2, des2, aflow);

    // fork: match on s2, gemm on the main (capturing) stream
    cudaEventRecord(ev_fork, 0);
    cudaStreamWaitEvent(s2, ev_fork, 0);

    k_match<<<NPTS, 128, 0, s2>>>(des2, qlt1, qlt2,
                                  out_scores, out_lab, out_mask, out_qlt);

    dim3 gg((NPTS + 127) / 128, (NPTS + 127) / 128);
    k_gemm<<<gg, 256>>>(out_scores, out_lab);

    // join
    cudaEventRecord(ev_join, s2);
    cudaStreamWaitEvent(0, ev_join, 0);
}

// round 15
// speedup vs baseline: 1.0644x; 1.0070x over previous
#include <cuda_runtime.h>
#include <cuda_bf16.h>

typedef unsigned int u32;

#define NPTS 3600
#define DD   128
#define HH   512
#define WW   512
#define NPB  900
#define WC   30
#define SCOLS 3601   // 1 + NPTS
#define SPITCH 40    // bf16 elements per smem row (conflict-free)

// ---------------- scratch (static device globals) ---------------------------
__device__ int   g_y1[NPTS], g_x1[NPTS];
__device__ int   g_yd[NPTS], g_xd[NPTS];
__device__ int   g_xy2x[NPTS], g_xy2y[NPTS];
__device__ float g_A[NPTS * DD];
__device__ uint4 g_Ahi[NPTS * DD / 8];
__device__ uint4 g_Alo[NPTS * DD / 8];
__device__ uint4 g_Bhi[NPTS * DD / 8];
__device__ uint4 g_Blo[NPTS * DD / 8];

__constant__ int c_OI[13] = {-2,-1,-1,-1, 0, 0, 0, 0, 0, 1, 1, 1, 2};
__constant__ int c_OJ[13] = { 0,-1, 0, 1,-2,-1, 0, 1, 2,-1, 0, 1, 0};

// ---------------- kernel 1: per-cell argmax sample + descriptor gather ------
__global__ void k_sample(const float* __restrict__ det1, const float* __restrict__ des1,
                         const float* __restrict__ det2, const float* __restrict__ des2,
                         const float* __restrict__ aflow)
{
    const int c = blockIdx.x;
    const int which = blockIdx.y;
    const float* det = which ? det2 : det1;
    const float* des = which ? des2 : des1;

    const int b = c / NPB;
    const int cell = c % NPB;
    const int hc = cell / WC;
    const int wc = cell % WC;
    const int t = threadIdx.x;
    const int row = 16 + hc * 16 + (t >> 4);
    const int col = 16 + wc * 16 + (t & 15);

    float v = det[((size_t)b * HH + row) * WW + col];

    __shared__ float sv[256];
    __shared__ int   si[256];
    sv[t] = v;
    si[t] = t;
    __syncthreads();
    for (int s = 128; s > 0; s >>= 1) {
        if (t < s) {
            float v2 = sv[t + s];
            int i2 = si[t + s];
            if (v2 > sv[t] || (v2 == sv[t] && i2 < si[t])) { sv[t] = v2; si[t] = i2; }
        }
        __syncthreads();
    }
    const int best = si[0];
    const int brow = 16 + hc * 16 + (best >> 4);  // axis3 index (x1 / xd)
    const int bcol = 16 + wc * 16 + (best & 15);  // axis2 index (y1 / yd)

    if (t == 0) {
        if (which == 0) {
            g_y1[c] = bcol;
            g_x1[c] = brow;
            const float ax = aflow[(((size_t)b * 2 + 0) * HH + bcol) * WW + brow];
            const float ay = aflow[(((size_t)b * 2 + 1) * HH + bcol) * WW + brow];
            g_xy2x[c] = (int)(ax + 0.5f);
            g_xy2y[c] = (int)(ay + 0.5f);
        } else {
            g_yd[c] = bcol;
            g_xd[c] = brow;
        }
    }
    if (t < DD) {
        float d = des[(((size_t)b * DD + t) * HH + bcol) * WW + brow];
        __nv_bfloat16 hi = __float2bfloat16(d);
        __nv_bfloat16 lo = __float2bfloat16(d - __bfloat162float(hi));
        const size_t idx = (size_t)c * DD + t;
        if (which == 0) {
            g_A[idx] = d;
            ((__nv_bfloat16*)g_Ahi)[idx] = hi;
            ((__nv_bfloat16*)g_Alo)[idx] = lo;
        } else {
            ((__nv_bfloat16*)g_Bhi)[idx] = hi;
            ((__nv_bfloat16*)g_Blo)[idx] = lo;
        }
    }
}

// ---------------- kernel 2: neighbor matching (one BLOCK per keypoint) ------
__global__ void __launch_bounds__(128)
k_match(const float* __restrict__ des2,
        const float* __restrict__ qlt1, const float* __restrict__ qlt2,
        float* __restrict__ out_scores, float* __restrict__ out_lab,
        float* __restrict__ out_mask, float* __restrict__ out_qlt)
{
    const int n = blockIdx.x;
    const int t = threadIdx.x;        // d channel 0..127
    const int lane = t & 31;
    const int warp = t >> 5;

    const int b  = n / NPB;
    const int xx = g_xy2x[n];
    const int yy = g_xy2y[n];

    const float s = g_A[(size_t)n * DD + t];

    const float* base = des2 + (size_t)b * DD * HH * WW + (size_t)t * HH * WW;

    float val[13];
    #pragma unroll
    for (int k = 0; k < 13; k++) {
        int px = xx + c_OI[k]; px = px < 0 ? 0 : (px > WW - 1 ? WW - 1 : px);
        int py = yy + c_OJ[k]; py = py < 0 ? 0 : (py > HH - 1 ? HH - 1 : py);
        val[k] = s * __ldg(&base[(size_t)py * WW + px]);
    }

    #pragma unroll
    for (int k = 0; k < 13; k++) {
        #pragma unroll
        for (int off = 16; off > 0; off >>= 1)
            val[k] += __shfl_xor_sync(0xffffffffu, val[k], off);
    }

    __shared__ float sred[4][13];
    if (lane == 0) {
        #pragma unroll
        for (int k = 0; k < 13; k++) sred[warp][k] = val[k];
    }
    __syncthreads();

    if (t == 0) {
        float dots[13];
        #pragma unroll
        for (int k = 0; k < 13; k++)
            dots[k] = sred[0][k] + sred[1][k] + sred[2][k] + sred[3][k];

        float best = dots[0];
        int pos = 0;
        #pragma unroll
        for (int k = 1; k < 13; k++)
            if (dots[k] > best) { best = dots[k]; pos = k; }

        const int y1 = g_y1[n];
        const int x1 = g_x1[n];
        const bool msk = (xx >= 0) && (yy >= 0) && (xx < WW) && (yy < HH);
        int sx = xx + c_OI[pos]; sx = sx < 0 ? 0 : (sx > WW - 1 ? WW - 1 : sx);
        int sy = yy + c_OJ[pos]; sy = sy < 0 ? 0 : (sy > HH - 1 ? HH - 1 : sy);
        float q = 0.5f * (qlt1[((size_t)b * HH + y1) * WW + x1] +
                          qlt2[((size_t)b * HH + sy) * WW + sx]);
        out_scores[(size_t)n * SCOLS] = best;
        out_lab[(size_t)n * SCOLS]    = 1.0f;
        out_qlt[n]  = q;
        out_mask[n] = msk ? 1.0f : 0.0f;
    }
}

// ---------------- kernel 3: bf16x3 tensor-core GEMM + mask + labels --------
__device__ __forceinline__ void ldsm_x4(u32 addr, u32* r)
{
    asm volatile("ldmatrix.sync.aligned.m8n8.x4.shared.b16 {%0,%1,%2,%3}, [%4];"
                 : "=r"(r[0]), "=r"(r[1]), "=r"(r[2]), "=r"(r[3]) : "r"(addr));
}

__device__ __forceinline__ void mma_bf16(float* c, const u32* a, const u32* b)
{
    asm volatile("mma.sync.aligned.m16n8k16.row.col.f32.bf16.bf16.f32 "
                 "{%0,%1,%2,%3}, {%4,%5,%6,%7}, {%8,%9}, {%0,%1,%2,%3};"
                 : "+f"(c[0]), "+f"(c[1]), "+f"(c[2]), "+f"(c[3])
                 : "r"(a[0]), "r"(a[1]), "r"(a[2]), "r"(a[3]), "r"(b[0]), "r"(b[1]));
}

__global__ void __launch_bounds__(256, 1)
k_gemm(float* __restrict__ out_scores, float* __restrict__ out_lab)
{
    __shared__ __align__(16) __nv_bfloat16 sAhi[128 * SPITCH];
    __shared__ __align__(16) __nv_bfloat16 sAlo[128 * SPITCH];
    __shared__ __align__(16) __nv_bfloat16 sBhi[128 * SPITCH];
    __shared__ __align__(16) __nv_bfloat16 sBlo[128 * SPITCH];

    const int tid    = threadIdx.x;
    const int warp   = tid >> 5;
    const int lane   = tid & 31;
    const int warp_m = warp >> 2;      // 0..1
    const int warp_n = warp & 3;       // 0..3
    const int m0 = blockIdx.y * 128;
    const int n0 = blockIdx.x * 128;

    const int g  = lane >> 2;          // fragment group row 0..7
    const int cp = (lane & 3) * 2;     // fragment col pair 0,2,4,6

    const u32 sAhi_b = (u32)__cvta_generic_to_shared(sAhi);
    const u32 sAlo_b = (u32)__cvta_generic_to_shared(sAlo);
    const u32 sBhi_b = (u32)__cvta_generic_to_shared(sBhi);
    const u32 sBlo_b = (u32)__cvta_generic_to_shared(sBlo);

    // ldmatrix source lane-addresses (within-tile row/col)
    const int a_row = warp_m * 64 + (lane & 15);          // + mt*16
    const int a_col = (lane >> 4) << 3;                   // + ks
    const int b_row = warp_n * 32 + ((lane >> 4) << 3) + (lane & 7);  // + np*16
    const int b_col = ((lane >> 3) & 1) << 3;             // + ks

    float acc[4][4][4];
    #pragma unroll
    for (int mt = 0; mt < 4; mt++) {
        #pragma unroll
        for (int nt = 0; nt < 4; nt++) {
            acc[mt][nt][0] = 0.f; acc[mt][nt][1] = 0.f;
            acc[mt][nt][2] = 0.f; acc[mt][nt][3] = 0.f;
        }
    }

    const int lr = tid >> 1;            // 0..127: tile row to load
    const int kh = (tid & 1) * 16;      // 16-elem half of the 32-k chunk
    const int ar = m0 + lr;
    const int br = n0 + lr;

    for (int kc = 0; kc < DD; kc += 32) {
        // prefetch globals BEFORE the sync so LDG latency overlaps prior mma
        uint4 z = make_uint4(0u, 0u, 0u, 0u);
        uint4 vah0 = z, vah1 = z, vlo0 = z, vlo1 = z;
        uint4 vbh0 = z, vbh1 = z, vbl0 = z, vbl1 = z;
        const int gi = (kc + kh) >> 3;              // uint4 index within row
        if (ar < NPTS) {
            vah0 = g_Ahi[(size_t)ar * (DD / 8) + gi];
            vah1 = g_Ahi[(size_t)ar * (DD / 8) + gi + 1];
            vlo0 = g_Alo[(size_t)ar * (DD / 8) + gi];
            vlo1 = g_Alo[(size_t)ar * (DD / 8) + gi + 1];
        }
        if (br < NPTS) {
            vbh0 = g_Bhi[(size_t)br * (DD / 8) + gi];
            vbh1 = g_Bhi[(size_t)br * (DD / 8) + gi + 1];
            vbl0 = g_Blo[(size_t)br * (DD / 8) + gi];
            vbl1 = g_Blo[(size_t)br * (DD / 8) + gi + 1];
        }
        __syncthreads();   // previous chunk's mma consumed the smem
        *(uint4*)&sAhi[lr * SPITCH + kh]     = vah0;
        *(uint4*)&sAhi[lr * SPITCH + kh + 8] = vah1;
        *(uint4*)&sAlo[lr * SPITCH + kh]     = vlo0;
        *(uint4*)&sAlo[lr * SPITCH + kh + 8] = vlo1;
        *(uint4*)&sBhi[lr * SPITCH + kh]     = vbh0;
        *(uint4*)&sBhi[lr * SPITCH + kh + 8] = vbh1;
        *(uint4*)&sBlo[lr * SPITCH + kh]     = vbl0;
        *(uint4*)&sBlo[lr * SPITCH + kh + 8] = vbl1;
        __syncthreads();

        #pragma unroll
        for (int ks = 0; ks < 32; ks += 16) {
            u32 Ahf[4][4];
            u32 Alf[4][4];
            u32 Bhf[4][2];
            u32 Blf[4][2];
            u32 tmp[4];

            #pragma unroll
            for (int mt = 0; mt < 4; mt++) {
                const u32 aoff = (u32)(((a_row + mt * 16) * SPITCH) + ks + a_col) * 2u;
                ldsm_x4(sAhi_b + aoff, Ahf[mt]);
                ldsm_x4(sAlo_b + aoff, Alf[mt]);
            }
            #pragma unroll
            for (int np = 0; np < 2; np++) {
                const u32 boff = (u32)(((b_row + np * 16) * SPITCH) + ks + b_col) * 2u;
                ldsm_x4(sBhi_b + boff, tmp);
                Bhf[2 * np][0]     = tmp[0]; Bhf[2 * np][1]     = tmp[1];
                Bhf[2 * np + 1][0] = tmp[2]; Bhf[2 * np + 1][1] = tmp[3];
                ldsm_x4(sBlo_b + boff, tmp);
                Blf[2 * np][0]     = tmp[0]; Blf[2 * np][1]     = tmp[1];
                Blf[2 * np + 1][0] = tmp[2]; Blf[2 * np + 1][1] = tmp[3];
            }
            #pragma unroll
            for (int mt = 0; mt < 4; mt++) {
                #pragma unroll
                for (int nt = 0; nt < 4; nt++) {
                    mma_bf16(acc[mt][nt], Ahf[mt], Bhf[nt]);
                    mma_bf16(acc[mt][nt], Ahf[mt], Blf[nt]);
                    mma_bf16(acc[mt][nt], Alf[mt], Bhf[nt]);
                }
            }
        }
    }

    // ---- epilogue: distance mask, write scores[:,1:] and labels[:,1:]=0 ----
    int rX[8], rY[8], rB[8], rI[8];
    #pragma unroll
    for (int idx = 0; idx < 8; idx++) {
        int mt = idx >> 1;
        int h  = idx & 1;
        int i  = m0 + warp_m * 64 + mt * 16 + g + h * 8;
        rI[idx] = (i < NPTS) ? i : -1;
        int iw = (i < NPTS) ? i : 0;
        rX[idx] = g_xy2x[iw];
        rY[idx] = g_xy2y[iw];
        rB[idx] = iw / NPB;
    }
    int cX[8], cY[8], cB[8], cJ[8];
    #pragma unroll
    for (int idx = 0; idx < 8; idx++) {
        int nt = idx >> 1;
        int e  = idx & 1;
        int j  = n0 + warp_n * 32 + nt * 8 + cp + e;
        cJ[idx] = (j < NPTS) ? j : -1;
        int jw = (j < NPTS) ? j : 0;
        cX[idx] = g_xd[jw];
        cY[idx] = g_yd[jw];
        cB[idx] = jw / NPB;
    }

    #pragma unroll
    for (int mt = 0; mt < 4; mt++) {
        #pragma unroll
        for (int nt = 0; nt < 4; nt++) {
            #pragma unroll
            for (int r = 0; r < 4; r++) {
                int ridx = mt * 2 + (r >> 1);
                int cidx = nt * 2 + (r & 1);
                int i = rI[ridx];
                int j = cJ[cidx];
                if (i < 0 || j < 0) continue;
                int dx = cX[cidx] - rX[ridx];
                int dy = cY[cidx] - rY[ridx];
                int dis2 = dx * dx + dy * dy + ((cB[cidx] != rB[ridx]) ? 4 : 0);
                float vout = (dis2 < 4) ? 0.f : acc[mt][nt][r];
                size_t o = (size_t)i * SCOLS + 1 + j;
                out_scores[o] = vout;
                out_lab[o] = 0.0f;
            }
        }
    }
}

// ---------------- launch: fork/join so match and gemm overlap ---------------
extern "C" void kernel_launch(void* const* d_in, const int* in_sizes, int n_in,
                              void* d_out, int out_size)
{
    static cudaStream_t s2 = 0;
    static cudaEvent_t ev_fork = 0, ev_join = 0;
    if (s2 == 0) {
        cudaStreamCreateWithFlags(&s2, cudaStreamNonBlocking);
        cudaEventCreateWithFlags(&ev_fork, cudaEventDisableTiming);
        cudaEventCreateWithFlags(&ev_join, cudaEventDisableTiming);
    }

    const float* des1  = (const float*)d_in[0];
    const float* det1  = (const float*)d_in[1];
    const float* qlt1  = (const float*)d_in[2];
    const float* des2  = (const float*)d_in[3];
    const float* det2  = (const float*)d_in[4];
    const float* qlt2  = (const float*)d_in[5];
    const float* aflow = (const float*)d_in[6];

    float* out        = (float*)d_out;
    float* out_scores = out;                                     // (3600, 3601)
    float* out_lab    = out + (size_t)NPTS * SCOLS;              // (3600, 3601)
    float* out_mask   = out_lab + (size_t)NPTS * SCOLS;          // (4, 900)
    float* out_qlt    = out_mask + NPTS;                         // (3600, 1)

    dim3 gs(NPTS, 2);
    k_sample<<<gs, 256>>>(det1, des1, det2, des2, aflow);

    // fork: match on s2, gemm on the main (capturing) stream
    cudaEventRecord(ev_fork, 0);
    cudaStreamWaitEvent(s2, ev_fork, 0);

    k_match<<<NPTS, 128, 0, s2>>>(des2, qlt1, qlt2,
                                  out_scores, out_lab, out_mask, out_qlt);

    dim3 gg((NPTS + 127) / 128, (NPTS + 127) / 128);
    k_gemm<<<gg, 256>>>(out_scores, out_lab);

    // join
    cudaEventRecord(ev_join, s2);
    cudaStreamWaitEvent(0, ev_join, 0);
}

// round 16
// speedup vs baseline: 1.0796x; 1.0142x over previous
#include <cuda_runtime.h>
#include <cuda_bf16.h>

typedef unsigned int u32;

#define NPTS 3600
#define DD   128
#define HH   512
#define WW   512
#define NPB  900
#define WC   30
#define SCOLS 3601   // 1 + NPTS
#define SPITCH 40    // bf16 elements per smem row (conflict-free)

// ---------------- scratch (static device globals) ---------------------------
__device__ int   g_y1[NPTS], g_x1[NPTS];
__device__ int   g_yd[NPTS], g_xd[NPTS];
__device__ int   g_xy2x[NPTS], g_xy2y[NPTS];
__device__ float g_A[NPTS * DD];
__device__ uint4 g_Ahi[NPTS * DD / 8];
__device__ uint4 g_Alo[NPTS * DD / 8];
__device__ uint4 g_Bhi[NPTS * DD / 8];
__device__ uint4 g_Blo[NPTS * DD / 8];

__constant__ int c_OI[13] = {-2,-1,-1,-1, 0, 0, 0, 0, 0, 1, 1, 1, 2};
__constant__ int c_OJ[13] = { 0,-1, 0, 1,-2,-1, 0, 1, 2,-1, 0, 1, 0};

// ---------------- kernel 1: per-cell argmax sample + descriptor gather ------
__global__ void k_sample(const float* __restrict__ det1, const float* __restrict__ des1,
                         const float* __restrict__ det2, const float* __restrict__ des2,
                         const float* __restrict__ aflow)
{
    const int c = blockIdx.x;
    const int which = blockIdx.y;
    const float* det = which ? det2 : det1;
    const float* des = which ? des2 : des1;

    const int b = c / NPB;
    const int cell = c % NPB;
    const int hc = cell / WC;
    const int wc = cell % WC;
    const int t = threadIdx.x;
    const int row = 16 + hc * 16 + (t >> 4);
    const int col = 16 + wc * 16 + (t & 15);

    float v = det[((size_t)b * HH + row) * WW + col];

    __shared__ float sv[256];
    __shared__ int   si[256];
    sv[t] = v;
    si[t] = t;
    __syncthreads();
    for (int s = 128; s > 0; s >>= 1) {
        if (t < s) {
            float v2 = sv[t + s];
            int i2 = si[t + s];
            if (v2 > sv[t] || (v2 == sv[t] && i2 < si[t])) { sv[t] = v2; si[t] = i2; }
        }
        __syncthreads();
    }
    const int best = si[0];
    const int brow = 16 + hc * 16 + (best >> 4);  // axis3 index (x1 / xd)
    const int bcol = 16 + wc * 16 + (best & 15);  // axis2 index (y1 / yd)

    if (t == 0) {
        if (which == 0) {
            g_y1[c] = bcol;
            g_x1[c] = brow;
            const float ax = aflow[(((size_t)b * 2 + 0) * HH + bcol) * WW + brow];
            const float ay = aflow[(((size_t)b * 2 + 1) * HH + bcol) * WW + brow];
            g_xy2x[c] = (int)(ax + 0.5f);
            g_xy2y[c] = (int)(ay + 0.5f);
        } else {
            g_yd[c] = bcol;
            g_xd[c] = brow;
        }
    }
    if (t < DD) {
        float d = des[(((size_t)b * DD + t) * HH + bcol) * WW + brow];
        __nv_bfloat16 hi = __float2bfloat16(d);
        __nv_bfloat16 lo = __float2bfloat16(d - __bfloat162float(hi));
        const size_t idx = (size_t)c * DD + t;
        if (which == 0) {
            g_A[idx] = d;
            ((__nv_bfloat16*)g_Ahi)[idx] = hi;
            ((__nv_bfloat16*)g_Alo)[idx] = lo;
        } else {
            ((__nv_bfloat16*)g_Bhi)[idx] = hi;
            ((__nv_bfloat16*)g_Blo)[idx] = lo;
        }
    }
}

// ---------------- kernel 2: neighbor matching (one BLOCK per keypoint) ------
__global__ void __launch_bounds__(128)
k_match(const float* __restrict__ des2,
        const float* __restrict__ qlt1, const float* __restrict__ qlt2,
        float* __restrict__ out_scores, float* __restrict__ out_lab,
        float* __restrict__ out_mask, float* __restrict__ out_qlt)
{
    const int n = blockIdx.x;
    const int t = threadIdx.x;        // d channel 0..127
    const int lane = t & 31;
    const int warp = t >> 5;

    const int b  = n / NPB;
    const int xx = g_xy2x[n];
    const int yy = g_xy2y[n];

    const float s = g_A[(size_t)n * DD + t];

    const float* base = des2 + (size_t)b * DD * HH * WW + (size_t)t * HH * WW;

    float val[13];
    #pragma unroll
    for (int k = 0; k < 13; k++) {
        int px = xx + c_OI[k]; px = px < 0 ? 0 : (px > WW - 1 ? WW - 1 : px);
        int py = yy + c_OJ[k]; py = py < 0 ? 0 : (py > HH - 1 ? HH - 1 : py);
        val[k] = s * __ldg(&base[(size_t)py * WW + px]);
    }

    #pragma unroll
    for (int k = 0; k < 13; k++) {
        #pragma unroll
        for (int off = 16; off > 0; off >>= 1)
            val[k] += __shfl_xor_sync(0xffffffffu, val[k], off);
    }

    __shared__ float sred[4][13];
    if (lane == 0) {
        #pragma unroll
        for (int k = 0; k < 13; k++) sred[warp][k] = val[k];
    }
    __syncthreads();

    if (t == 0) {
        float dots[13];
        #pragma unroll
        for (int k = 0; k < 13; k++)
            dots[k] = sred[0][k] + sred[1][k] + sred[2][k] + sred[3][k];

        float best = dots[0];
        int pos = 0;
        #pragma unroll
        for (int k = 1; k < 13; k++)
            if (dots[k] > best) { best = dots[k]; pos = k; }

        const int y1 = g_y1[n];
        const int x1 = g_x1[n];
        const bool msk = (xx >= 0) && (yy >= 0) && (xx < WW) && (yy < HH);
        int sx = xx + c_OI[pos]; sx = sx < 0 ? 0 : (sx > WW - 1 ? WW - 1 : sx);
        int sy = yy + c_OJ[pos]; sy = sy < 0 ? 0 : (sy > HH - 1 ? HH - 1 : sy);
        float q = 0.5f * (qlt1[((size_t)b * HH + y1) * WW + x1] +
                          qlt2[((size_t)b * HH + sy) * WW + sx]);
        out_scores[(size_t)n * SCOLS] = best;
        out_lab[(size_t)n * SCOLS]    = 1.0f;
        out_qlt[n]  = q;
        out_mask[n] = msk ? 1.0f : 0.0f;
    }
}

// ---------------- kernel 3: bf16x3 tensor-core GEMM (512 thr, 16 warps) ----
__device__ __forceinline__ void ldsm_x4(u32 addr, u32* r)
{
    asm volatile("ldmatrix.sync.aligned.m8n8.x4.shared.b16 {%0,%1,%2,%3}, [%4];"
                 : "=r"(r[0]), "=r"(r[1]), "=r"(r[2]), "=r"(r[3]) : "r"(addr));
}

__device__ __forceinline__ void mma_bf16(float* c, const u32* a, const u32* b)
{
    asm volatile("mma.sync.aligned.m16n8k16.row.col.f32.bf16.bf16.f32 "
                 "{%0,%1,%2,%3}, {%4,%5,%6,%7}, {%8,%9}, {%0,%1,%2,%3};"
                 : "+f"(c[0]), "+f"(c[1]), "+f"(c[2]), "+f"(c[3])
                 : "r"(a[0]), "r"(a[1]), "r"(a[2]), "r"(a[3]), "r"(b[0]), "r"(b[1]));
}

__global__ void __launch_bounds__(512, 1)
k_gemm(float* __restrict__ out_scores, float* __restrict__ out_lab)
{
    __shared__ __align__(16) __nv_bfloat16 sAhi[128 * SPITCH];
    __shared__ __align__(16) __nv_bfloat16 sAlo[128 * SPITCH];
    __shared__ __align__(16) __nv_bfloat16 sBhi[128 * SPITCH];
    __shared__ __align__(16) __nv_bfloat16 sBlo[128 * SPITCH];

    const int tid    = threadIdx.x;
    const int warp   = tid >> 5;       // 0..15
    const int lane   = tid & 31;
    const int warp_m = warp >> 2;      // 0..3 (32 rows each)
    const int warp_n = warp & 3;       // 0..3 (32 cols each)
    const int m0 = blockIdx.y * 128;
    const int n0 = blockIdx.x * 128;

    const int g  = lane >> 2;          // fragment group row 0..7
    const int cp = (lane & 3) * 2;     // fragment col pair 0,2,4,6

    const u32 sAhi_b = (u32)__cvta_generic_to_shared(sAhi);
    const u32 sAlo_b = (u32)__cvta_generic_to_shared(sAlo);
    const u32 sBhi_b = (u32)__cvta_generic_to_shared(sBhi);
    const u32 sBlo_b = (u32)__cvta_generic_to_shared(sBlo);

    // ldmatrix source lane-addresses (within-tile row/col)
    const int a_row = warp_m * 32 + (lane & 15);                       // + mt*16
    const int a_col = (lane >> 4) << 3;                                // + ks
    const int b_row = warp_n * 32 + ((lane >> 4) << 3) + (lane & 7);   // + np*16
    const int b_col = ((lane >> 3) & 1) << 3;                          // + ks

    float acc[2][4][4];
    #pragma unroll
    for (int mt = 0; mt < 2; mt++) {
        #pragma unroll
        for (int nt = 0; nt < 4; nt++) {
            acc[mt][nt][0] = 0.f; acc[mt][nt][1] = 0.f;
            acc[mt][nt][2] = 0.f; acc[mt][nt][3] = 0.f;
        }
    }

    const int lr = tid >> 2;            // 0..127: tile row to load
    const int kh = (tid & 3) * 8;       // 8-elem (one uint4) slice of k32 chunk
    const int ar = m0 + lr;
    const int br = n0 + lr;

    for (int kc = 0; kc < DD; kc += 32) {
        // prefetch globals BEFORE the sync so LDG latency overlaps prior mma
        uint4 z = make_uint4(0u, 0u, 0u, 0u);
        uint4 vah = z, vlo = z, vbh = z, vbl = z;
        const int gi = (kc + kh) >> 3;              // uint4 index within row
        if (ar < NPTS) {
            vah = g_Ahi[(size_t)ar * (DD / 8) + gi];
            vlo = g_Alo[(size_t)ar * (DD / 8) + gi];
        }
        if (br < NPTS) {
            vbh = g_Bhi[(size_t)br * (DD / 8) + gi];
            vbl = g_Blo[(size_t)br * (DD / 8) + gi];
        }
        __syncthreads();   // previous chunk's mma consumed the smem
        *(uint4*)&sAhi[lr * SPITCH + kh] = vah;
        *(uint4*)&sAlo[lr * SPITCH + kh] = vlo;
        *(uint4*)&sBhi[lr * SPITCH + kh] = vbh;
        *(uint4*)&sBlo[lr * SPITCH + kh] = vbl;
        __syncthreads();

        #pragma unroll
        for (int ks = 0; ks < 32; ks += 16) {
            u32 Ahf[2][4];
            u32 Alf[2][4];
            u32 Bhf[4][2];
            u32 Blf[4][2];
            u32 tmp[4];

            #pragma unroll
            for (int mt = 0; mt < 2; mt++) {
                const u32 aoff = (u32)(((a_row + mt * 16) * SPITCH) + ks + a_col) * 2u;
                ldsm_x4(sAhi_b + aoff, Ahf[mt]);
                ldsm_x4(sAlo_b + aoff, Alf[mt]);
            }
            #pragma unroll
            for (int np = 0; np < 2; np++) {
                const u32 boff = (u32)(((b_row + np * 16) * SPITCH) + ks + b_col) * 2u;
                ldsm_x4(sBhi_b + boff, tmp);
                Bhf[2 * np][0]     = tmp[0]; Bhf[2 * np][1]     = tmp[1];
                Bhf[2 * np + 1][0] = tmp[2]; Bhf[2 * np + 1][1] = tmp[3];
                ldsm_x4(sBlo_b + boff, tmp);
                Blf[2 * np][0]     = tmp[0]; Blf[2 * np][1]     = tmp[1];
                Blf[2 * np + 1][0] = tmp[2]; Blf[2 * np + 1][1] = tmp[3];
            }
            #pragma unroll
            for (int mt = 0; mt < 2; mt++) {
                #pragma unroll
                for (int nt = 0; nt < 4; nt++) {
                    mma_bf16(acc[mt][nt], Ahf[mt], Bhf[nt]);
                    mma_bf16(acc[mt][nt], Ahf[mt], Blf[nt]);
                    mma_bf16(acc[mt][nt], Alf[mt], Bhf[nt]);
                }
            }
        }
    }

    // ---- epilogue: distance mask, write scores[:,1:] and labels[:,1:]=0 ----
    int rX[4], rY[4], rB[4], rI[4];
    #pragma unroll
    for (int idx = 0; idx < 4; idx++) {
        int mt = idx >> 1;
        int h  = idx & 1;
        int i  = m0 + warp_m * 32 + mt * 16 + g + h * 8;
        rI[idx] = (i < NPTS) ? i : -1;
        int iw = (i < NPTS) ? i : 0;
        rX[idx] = g_xy2x[iw];
        rY[idx] = g_xy2y[iw];
        rB[idx] = iw / NPB;
    }
    int cX[8], cY[8], cB[8], cJ[8];
    #pragma unroll
    for (int idx = 0; idx < 8; idx++) {
        int nt = idx >> 1;
        int e  = idx & 1;
        int j  = n0 + warp_n * 32 + nt * 8 + cp + e;
        cJ[idx] = (j < NPTS) ? j : -1;
        int jw = (j < NPTS) ? j : 0;
        cX[idx] = g_xd[jw];
        cY[idx] = g_yd[jw];
        cB[idx] = jw / NPB;
    }

    #pragma unroll
    for (int mt = 0; mt < 2; mt++) {
        #pragma unroll
        for (int nt = 0; nt < 4; nt++) {
            #pragma unroll
            for (int r = 0; r < 4; r++) {
                int ridx = mt * 2 + (r >> 1);
                int cidx = nt * 2 + (r & 1);
                int i = rI[ridx];
                int j = cJ[cidx];
                if (i < 0 || j < 0) continue;
                int dx = cX[cidx] - rX[ridx];
                int dy = cY[cidx] - rY[ridx];
                int dis2 = dx * dx + dy * dy + ((cB[cidx] != rB[ridx]) ? 4 : 0);
                float vout = (dis2 < 4) ? 0.f : acc[mt][nt][r];
                size_t o = (size_t)i * SCOLS + 1 + j;
                out_scores[o] = vout;
                out_lab[o] = 0.0f;
            }
        }
    }
}

// ---------------- launch: fork/join so match and gemm overlap ---------------
extern "C" void kernel_launch(void* const* d_in, const int* in_sizes, int n_in,
                              void* d_out, int out_size)
{
    static cudaStream_t s2 = 0;
    static cudaEvent_t ev_fork = 0, ev_join = 0;
    if (s2 == 0) {
        cudaStreamCreateWithFlags(&s2, cudaStreamNonBlocking);
        cudaEventCreateWithFlags(&ev_fork, cudaEventDisableTiming);
        cudaEventCreateWithFlags(&ev_join, cudaEventDisableTiming);
    }

    const float* des1  = (const float*)d_in[0];
    const float* det1  = (const float*)d_in[1];
    const float* qlt1  = (const float*)d_in[2];
    const float* des2  = (const float*)d_in[3];
    const float* det2  = (const float*)d_in[4];
    const float* qlt2  = (const float*)d_in[5];
    const float* aflow = (const float*)d_in[6];

    float* out        = (float*)d_out;
    float* out_scores = out;                                     // (3600, 3601)
    float* out_lab    = out + (size_t)NPTS * SCOLS;              // (3600, 3601)
    float* out_mask   = out_lab + (size_t)NPTS * SCOLS;          // (4, 900)
    float* out_qlt    = out_mask + NPTS;                         // (3600, 1)

    dim3 gs(NPTS, 2);
    k_sample<<<gs, 256>>>(det1, des1, det2, des2, aflow);

    // fork: match on s2, gemm on the main (capturing) stream
    cudaEventRecord(ev_fork, 0);
    cudaStreamWaitEvent(s2, ev_fork, 0);

    k_match<<<NPTS, 128, 0, s2>>>(des2, qlt1, qlt2,
                                  out_scores, out_lab, out_mask, out_qlt);

    dim3 gg((NPTS + 127) / 128, (NPTS + 127) / 128);
    k_gemm<<<gg, 512>>>(out_scores, out_lab);

    // join
    cudaEventRecord(ev_join, s2);
    cudaStreamWaitEvent(0, ev_join, 0);
}

// round 17
// speedup vs baseline: 1.3008x; 1.2049x over previous
#include <cuda_runtime.h>
#include <cuda_bf16.h>

typedef unsigned int u32;

#define NPTS 3600
#define DD   128
#define HH   512
#define WW   512
#define NPB  900
#define WC   30
#define SCOLS 3601   // 1 + NPTS
#define SPITCH 40    // bf16 elements per smem row (conflict-free)

// ---------------- scratch (static device globals) ---------------------------
__device__ int   g_y1[NPTS], g_x1[NPTS];
__device__ int   g_yd[NPTS], g_xd[NPTS];
__device__ int   g_xy2x[NPTS], g_xy2y[NPTS];
__device__ float g_A[NPTS * DD];
__device__ uint4 g_Ahi[NPTS * DD / 8];
__device__ uint4 g_Alo[NPTS * DD / 8];
__device__ uint4 g_Bhi[NPTS * DD / 8];
__device__ uint4 g_Blo[NPTS * DD / 8];

__constant__ int c_OI[13] = {-2,-1,-1,-1, 0, 0, 0, 0, 0, 1, 1, 1, 2};
__constant__ int c_OJ[13] = { 0,-1, 0, 1,-2,-1, 0, 1, 2,-1, 0, 1, 0};

// ---------------- kernel 0: stream-fill labels plane with zeros -------------
// labels = NPTS*SCOLS floats, divisible by 4; match sets col 0 to 1 later.
__global__ void k_labels(float4* __restrict__ lab4)
{
    const size_t total = (size_t)NPTS * SCOLS / 4;
    const float4 z = make_float4(0.f, 0.f, 0.f, 0.f);
    for (size_t i = (size_t)blockIdx.x * blockDim.x + threadIdx.x;
         i < total; i += (size_t)gridDim.x * blockDim.x)
        lab4[i] = z;
}

// ---------------- kernel 1: per-cell argmax sample + descriptor gather ------
__global__ void k_sample(const float* __restrict__ det1, const float* __restrict__ des1,
                         const float* __restrict__ det2, const float* __restrict__ des2,
                         const float* __restrict__ aflow)
{
    const int c = blockIdx.x;
    const int which = blockIdx.y;
    const float* det = which ? det2 : det1;
    const float* des = which ? des2 : des1;

    const int b = c / NPB;
    const int cell = c % NPB;
    const int hc = cell / WC;
    const int wc = cell % WC;
    const int t = threadIdx.x;
    const int row = 16 + hc * 16 + (t >> 4);
    const int col = 16 + wc * 16 + (t & 15);

    float v = det[((size_t)b * HH + row) * WW + col];

    __shared__ float sv[256];
    __shared__ int   si[256];
    sv[t] = v;
    si[t] = t;
    __syncthreads();
    for (int s = 128; s > 0; s >>= 1) {
        if (t < s) {
            float v2 = sv[t + s];
            int i2 = si[t + s];
            if (v2 > sv[t] || (v2 == sv[t] && i2 < si[t])) { sv[t] = v2; si[t] = i2; }
        }
        __syncthreads();
    }
    const int best = si[0];
    const int brow = 16 + hc * 16 + (best >> 4);  // axis3 index (x1 / xd)
    const int bcol = 16 + wc * 16 + (best & 15);  // axis2 index (y1 / yd)

    if (t == 0) {
        if (which == 0) {
            g_y1[c] = bcol;
            g_x1[c] = brow;
            const float ax = aflow[(((size_t)b * 2 + 0) * HH + bcol) * WW + brow];
            const float ay = aflow[(((size_t)b * 2 + 1) * HH + bcol) * WW + brow];
            g_xy2x[c] = (int)(ax + 0.5f);
            g_xy2y[c] = (int)(ay + 0.5f);
        } else {
            g_yd[c] = bcol;
            g_xd[c] = brow;
        }
    }
    if (t < DD) {
        float d = des[(((size_t)b * DD + t) * HH + bcol) * WW + brow];
        __nv_bfloat16 hi = __float2bfloat16(d);
        __nv_bfloat16 lo = __float2bfloat16(d - __bfloat162float(hi));
        const size_t idx = (size_t)c * DD + t;
        if (which == 0) {
            g_A[idx] = d;
            ((__nv_bfloat16*)g_Ahi)[idx] = hi;
            ((__nv_bfloat16*)g_Alo)[idx] = lo;
        } else {
            ((__nv_bfloat16*)g_Bhi)[idx] = hi;
            ((__nv_bfloat16*)g_Blo)[idx] = lo;
        }
    }
}

// ---------------- kernel 2: neighbor matching (one BLOCK per keypoint) ------
__global__ void __launch_bounds__(128)
k_match(const float* __restrict__ des2,
        const float* __restrict__ qlt1, const float* __restrict__ qlt2,
        float* __restrict__ out_scores, float* __restrict__ out_lab,
        float* __restrict__ out_mask, float* __restrict__ out_qlt)
{
    const int n = blockIdx.x;
    const int t = threadIdx.x;        // d channel 0..127
    const int lane = t & 31;
    const int warp = t >> 5;

    const int b  = n / NPB;
    const int xx = g_xy2x[n];
    const int yy = g_xy2y[n];

    const float s = g_A[(size_t)n * DD + t];

    const float* base = des2 + (size_t)b * DD * HH * WW + (size_t)t * HH * WW;

    float val[13];
    #pragma unroll
    for (int k = 0; k < 13; k++) {
        int px = xx + c_OI[k]; px = px < 0 ? 0 : (px > WW - 1 ? WW - 1 : px);
        int py = yy + c_OJ[k]; py = py < 0 ? 0 : (py > HH - 1 ? HH - 1 : py);
        val[k] = s * __ldg(&base[(size_t)py * WW + px]);
    }

    #pragma unroll
    for (int k = 0; k < 13; k++) {
        #pragma unroll
        for (int off = 16; off > 0; off >>= 1)
            val[k] += __shfl_xor_sync(0xffffffffu, val[k], off);
    }

    __shared__ float sred[4][13];
    if (lane == 0) {
        #pragma unroll
        for (int k = 0; k < 13; k++) sred[warp][k] = val[k];
    }
    __syncthreads();

    if (t == 0) {
        float dots[13];
        #pragma unroll
        for (int k = 0; k < 13; k++)
            dots[k] = sred[0][k] + sred[1][k] + sred[2][k] + sred[3][k];

        float best = dots[0];
        int pos = 0;
        #pragma unroll
        for (int k = 1; k < 13; k++)
            if (dots[k] > best) { best = dots[k]; pos = k; }

        const int y1 = g_y1[n];
        const int x1 = g_x1[n];
        const bool msk = (xx >= 0) && (yy >= 0) && (xx < WW) && (yy < HH);
        int sx = xx + c_OI[pos]; sx = sx < 0 ? 0 : (sx > WW - 1 ? WW - 1 : sx);
        int sy = yy + c_OJ[pos]; sy = sy < 0 ? 0 : (sy > HH - 1 ? HH - 1 : sy);
        float q = 0.5f * (qlt1[((size_t)b * HH + y1) * WW + x1] +
                          qlt2[((size_t)b * HH + sy) * WW + sx]);
        out_scores[(size_t)n * SCOLS] = best;
        out_lab[(size_t)n * SCOLS]    = 1.0f;   // labels plane pre-zeroed by k_labels
        out_qlt[n]  = q;
        out_mask[n] = msk ? 1.0f : 0.0f;
    }
}

// ---------------- kernel 3: bf16x3 tensor-core GEMM (512 thr, 16 warps) ----
__device__ __forceinline__ void ldsm_x4(u32 addr, u32* r)
{
    asm volatile("ldmatrix.sync.aligned.m8n8.x4.shared.b16 {%0,%1,%2,%3}, [%4];"
                 : "=r"(r[0]), "=r"(r[1]), "=r"(r[2]), "=r"(r[3]) : "r"(addr));
}

__device__ __forceinline__ void mma_bf16(float* c, const u32* a, const u32* b)
{
    asm volatile("mma.sync.aligned.m16n8k16.row.col.f32.bf16.bf16.f32 "
                 "{%0,%1,%2,%3}, {%4,%5,%6,%7}, {%8,%9}, {%0,%1,%2,%3};"
                 : "+f"(c[0]), "+f"(c[1]), "+f"(c[2]), "+f"(c[3])
                 : "r"(a[0]), "r"(a[1]), "r"(a[2]), "r"(a[3]), "r"(b[0]), "r"(b[1]));
}

__global__ void __launch_bounds__(512, 1)
k_gemm(float* __restrict__ out_scores)
{
    __shared__ __align__(16) __nv_bfloat16 sAhi[128 * SPITCH];
    __shared__ __align__(16) __nv_bfloat16 sAlo[128 * SPITCH];
    __shared__ __align__(16) __nv_bfloat16 sBhi[128 * SPITCH];
    __shared__ __align__(16) __nv_bfloat16 sBlo[128 * SPITCH];

    const int tid    = threadIdx.x;
    const int warp   = tid >> 5;       // 0..15
    const int lane   = tid & 31;
    const int warp_m = warp >> 2;      // 0..3 (32 rows each)
    const int warp_n = warp & 3;       // 0..3 (32 cols each)
    const int m0 = blockIdx.y * 128;
    const int n0 = blockIdx.x * 128;

    const int g  = lane >> 2;          // fragment group row 0..7
    const int cp = (lane & 3) * 2;     // fragment col pair 0,2,4,6

    const u32 sAhi_b = (u32)__cvta_generic_to_shared(sAhi);
    const u32 sAlo_b = (u32)__cvta_generic_to_shared(sAlo);
    const u32 sBhi_b = (u32)__cvta_generic_to_shared(sBhi);
    const u32 sBlo_b = (u32)__cvta_generic_to_shared(sBlo);

    const int a_row = warp_m * 32 + (lane & 15);                       // + mt*16
    const int a_col = (lane >> 4) << 3;                                // + ks
    const int b_row = warp_n * 32 + ((lane >> 4) << 3) + (lane & 7);   // + np*16
    const int b_col = ((lane >> 3) & 1) << 3;                          // + ks

    float acc[2][4][4];
    #pragma unroll
    for (int mt = 0; mt < 2; mt++) {
        #pragma unroll
        for (int nt = 0; nt < 4; nt++) {
            acc[mt][nt][0] = 0.f; acc[mt][nt][1] = 0.f;
            acc[mt][nt][2] = 0.f; acc[mt][nt][3] = 0.f;
        }
    }

    const int lr = tid >> 2;            // 0..127: tile row to load
    const int kh = (tid & 3) * 8;       // 8-elem (one uint4) slice of k32 chunk
    const int ar = m0 + lr;
    const int br = n0 + lr;

    for (int kc = 0; kc < DD; kc += 32) {
        uint4 z = make_uint4(0u, 0u, 0u, 0u);
        uint4 vah = z, vlo = z, vbh = z, vbl = z;
        const int gi = (kc + kh) >> 3;
        if (ar < NPTS) {
            vah = g_Ahi[(size_t)ar * (DD / 8) + gi];
            vlo = g_Alo[(size_t)ar * (DD / 8) + gi];
        }
        if (br < NPTS) {
            vbh = g_Bhi[(size_t)br * (DD / 8) + gi];
            vbl = g_Blo[(size_t)br * (DD / 8) + gi];
        }
        __syncthreads();
        *(uint4*)&sAhi[lr * SPITCH + kh] = vah;
        *(uint4*)&sAlo[lr * SPITCH + kh] = vlo;
        *(uint4*)&sBhi[lr * SPITCH + kh] = vbh;
        *(uint4*)&sBlo[lr * SPITCH + kh] = vbl;
        __syncthreads();

        #pragma unroll
        for (int ks = 0; ks < 32; ks += 16) {
            u32 Ahf[2][4];
            u32 Alf[2][4];
            u32 Bhf[4][2];
            u32 Blf[4][2];
            u32 tmp[4];

            #pragma unroll
            for (int mt = 0; mt < 2; mt++) {
                const u32 aoff = (u32)(((a_row + mt * 16) * SPITCH) + ks + a_col) * 2u;
                ldsm_x4(sAhi_b + aoff, Ahf[mt]);
                ldsm_x4(sAlo_b + aoff, Alf[mt]);
            }
            #pragma unroll
            for (int np = 0; np < 2; np++) {
                const u32 boff = (u32)(((b_row + np * 16) * SPITCH) + ks + b_col) * 2u;
                ldsm_x4(sBhi_b + boff, tmp);
                Bhf[2 * np][0]     = tmp[0]; Bhf[2 * np][1]     = tmp[1];
                Bhf[2 * np + 1][0] = tmp[2]; Bhf[2 * np + 1][1] = tmp[3];
                ldsm_x4(sBlo_b + boff, tmp);
                Blf[2 * np][0]     = tmp[0]; Blf[2 * np][1]     = tmp[1];
                Blf[2 * np + 1][0] = tmp[2]; Blf[2 * np + 1][1] = tmp[3];
            }
            #pragma unroll
            for (int mt = 0; mt < 2; mt++) {
                #pragma unroll
                for (int nt = 0; nt < 4; nt++) {
                    mma_bf16(acc[mt][nt], Ahf[mt], Bhf[nt]);
                    mma_bf16(acc[mt][nt], Ahf[mt], Blf[nt]);
                    mma_bf16(acc[mt][nt], Alf[mt], Bhf[nt]);
                }
            }
        }
    }

    // ---- epilogue: distance mask + scores[:,1:] (labels handled elsewhere) -
    int rX[4], rY[4], rB[4], rI[4];
    #pragma unroll
    for (int idx = 0; idx < 4; idx++) {
        int mt = idx >> 1;
        int h  = idx & 1;
        int i  = m0 + warp_m * 32 + mt * 16 + g + h * 8;
        rI[idx] = (i < NPTS) ? i : -1;
        int iw = (i < NPTS) ? i : 0;
        rX[idx] = g_xy2x[iw];
        rY[idx] = g_xy2y[iw];
        rB[idx] = iw / NPB;
    }
    int cX[8], cY[8], cB[8], cJ[8];
    #pragma unroll
    for (int idx = 0; idx < 8; idx++) {
        int nt = idx >> 1;
        int e  = idx & 1;
        int j  = n0 + warp_n * 32 + nt * 8 + cp + e;
        cJ[idx] = (j < NPTS) ? j : -1;
        int jw = (j < NPTS) ? j : 0;
        cX[idx] = g_xd[jw];
        cY[idx] = g_yd[jw];
        cB[idx] = jw / NPB;
    }

    #pragma unroll
    for (int mt = 0; mt < 2; mt++) {
        #pragma unroll
        for (int nt = 0; nt < 4; nt++) {
            #pragma unroll
            for (int r = 0; r < 4; r++) {
                int ridx = mt * 2 + (r >> 1);
                int cidx = nt * 2 + (r & 1);
                int i = rI[ridx];
                int j = cJ[cidx];
                if (i < 0 || j < 0) continue;
                int dx = cX[cidx] - rX[ridx];
                int dy = cY[cidx] - rY[ridx];
                int dis2 = dx * dx + dy * dy + ((cB[cidx] != rB[ridx]) ? 4 : 0);
                float vout = (dis2 < 4) ? 0.f : acc[mt][nt][r];
                out_scores[(size_t)i * SCOLS + 1 + j] = vout;
            }
        }
    }
}

// ---------------- launch -----------------------------------------------------
extern "C" void kernel_launch(void* const* d_in, const int* in_sizes, int n_in,
                              void* d_out, int out_size)
{
    static cudaStream_t s2 = 0;
    static cudaEvent_t ev_fork = 0, ev_join = 0;
    if (s2 == 0) {
        cudaStreamCreateWithFlags(&s2, cudaStreamNonBlocking);
        cudaEventCreateWithFlags(&ev_fork, cudaEventDisableTiming);
        cudaEventCreateWithFlags(&ev_join, cudaEventDisableTiming);
    }

    const float* des1  = (const float*)d_in[0];
    const float* det1  = (const float*)d_in[1];
    const float* qlt1  = (const float*)d_in[2];
    const float* des2  = (const float*)d_in[3];
    const float* det2  = (const float*)d_in[4];
    const float* qlt2  = (const float*)d_in[5];
    const float* aflow = (const float*)d_in[6];

    float* out        = (float*)d_out;
    float* out_scores = out;                                     // (3600, 3601)
    float* out_lab    = out + (size_t)NPTS * SCOLS;              // (3600, 3601)
    float* out_mask   = out_lab + (size_t)NPTS * SCOLS;          // (4, 900)
    float* out_qlt    = out_mask + NPTS;                         // (3600, 1)

    // labels zero-fill on s2, concurrent with k_sample on the main stream
    k_labels<<<2048, 256, 0, s2>>>((float4*)out_lab);

    dim3 gs(NPTS, 2);
    k_sample<<<gs, 256>>>(det1, des1, det2, des2, aflow);

    // fork: match on s2 (after labels fill), gemm on the main stream
    cudaEventRecord(ev_fork, 0);
    cudaStreamWaitEvent(s2, ev_fork, 0);

    k_match<<<NPTS, 128, 0, s2>>>(des2, qlt1, qlt2,
                                  out_scores, out_lab, out_mask, out_qlt);

    dim3 gg((NPTS + 127) / 128, (NPTS + 127) / 128);
    k_gemm<<<gg, 512>>>(out_scores);

    // join
    cudaEventRecord(ev_join, s2);
    cudaStreamWaitEvent(0, ev_join, 0);
}